// round 14
// baseline (speedup 1.0000x reference)
#include <cuda_runtime.h>
#include <cuda_bf16.h>
#include <cstdint>
#include <math.h>

// ---------------------------------------------------------------------------
#define PIX33 1089
#define PITCH33 1092
#define PIXPAD 1152
#define PIX65 4225
#define PIX129 16641
#define CIN 128
#define COUT 768
#define NB 8
#define NCH 19
#define NSLICE 4

typedef unsigned long long u64;

__device__ __forceinline__ u64 pack2(float lo, float hi) {
    u64 r; asm("mov.b64 %0, {%1, %2};" : "=l"(r) : "f"(lo), "f"(hi)); return r;
}
__device__ __forceinline__ void unpack2(float& lo, float& hi, u64 v) {
    asm("mov.b64 {%0, %1}, %2;" : "=f"(lo), "=f"(hi) : "l"(v));
}
__device__ __forceinline__ void fma2(u64& d, u64 a, u64 b) {
    asm("fma.rn.f32x2 %0, %1, %2, %3;" : "=l"(d) : "l"(a), "l"(b), "l"(d));
}
__device__ __forceinline__ void mma16816(float* c, uint32_t a0, uint32_t a1,
                                         uint32_t a2, uint32_t a3,
                                         uint32_t b0, uint32_t b1) {
    asm volatile(
        "mma.sync.aligned.m16n8k16.row.col.f32.bf16.bf16.f32 "
        "{%0,%1,%2,%3}, {%4,%5,%6,%7}, {%8,%9}, {%0,%1,%2,%3};"
        : "+f"(c[0]), "+f"(c[1]), "+f"(c[2]), "+f"(c[3])
        : "r"(a0), "r"(a1), "r"(a2), "r"(a3), "r"(b0), "r"(b1));
}
__device__ __forceinline__ void ldsm4(uint32_t& r0, uint32_t& r1,
                                      uint32_t& r2, uint32_t& r3, uint32_t addr) {
    asm volatile("ldmatrix.sync.aligned.m8n8.x4.shared.b16 {%0,%1,%2,%3}, [%4];"
                 : "=r"(r0), "=r"(r1), "=r"(r2), "=r"(r3) : "r"(addr));
}
__device__ __forceinline__ uint32_t f2bf(float a, float b) {
    __nv_bfloat162 h = __floats2bfloat162_rn(a, b);
    return *(uint32_t*)&h;
}

__device__ __align__(16) __nv_bfloat16 g_Wbf[COUT * CIN];        // [o][k]
__device__ __align__(16) __nv_bfloat16 g_Sbf[NB * PIXPAD * CIN]; // [b][pix][k]
__device__ __align__(16) float g_y33[NB * COUT * PITCH33];
__device__ __align__(16) float g_Ut[NB * NCH * PIX129];
__device__ __align__(16) float g_Us[NB * NCH * PIX129];
__device__ __align__(16) float g_part[NSLICE][NB][4][PIX65];
__device__ double g_pi;
__device__ double g_d[2][NB * NCH];
__device__ double g_Wz[2][NB * NCH];
__device__ double g_R[2][NB][190];

static cudaStream_t g_s2;
static cudaEvent_t g_e1, g_e2;
namespace {
struct StreamInit {
    StreamInit() {
        cudaStreamCreateWithFlags(&g_s2, cudaStreamNonBlocking);
        cudaEventCreateWithFlags(&g_e1, cudaEventDisableTiming);
        cudaEventCreateWithFlags(&g_e2, cudaEventDisableTiming);
    }
};
static StreamInit g_si;
}

// ---------------------------------------------------------------------------
__global__ void zero_kernel() {
    int t = blockIdx.x * blockDim.x + threadIdx.x;
    if (t == 0) g_pi = 0.0;
    if (t < 2 * NB * 190) ((double*)g_R)[t] = 0.0;
}

// s_out fp32 [b][c][pix] -> bf16 transposed [b][pix][c], 32 channels/block.
// Folds the W fp32->bf16 convert into the b==0 blocks.
__global__ __launch_bounds__(256) void sbf_kernel(const float* __restrict__ s_out,
                                                  const float* __restrict__ conv_w) {
    __shared__ float t[64][33];
    int b = blockIdx.y, p0 = blockIdx.x * 64, cg = blockIdx.z * 32;
    int tid = threadIdx.x;

    if (b == 0) {
        int flat = blockIdx.x * 4 + blockIdx.z;     // 0..71
        for (int idx = flat * 256 + tid; idx < COUT * CIN; idx += 72 * 256)
            g_Wbf[idx] = __float2bfloat16(conv_w[idx]);
    }

    int px = tid & 63, c4 = tid >> 6;
    const float* base = s_out + (size_t)b * CIN * PIX33;
#pragma unroll
    for (int c0 = 0; c0 < 32; c0 += 4) {
        int c = c0 + c4;
        int pix = p0 + px;
        t[px][c] = (pix < PIX33) ? base[(size_t)(cg + c) * PIX33 + pix] : 0.f;
    }
    __syncthreads();
#pragma unroll
    for (int i = 0; i < 4; i++) {
        int id = tid + i * 256;
        int r = id >> 4, cp = id & 15;
        *(uint32_t*)&g_Sbf[((size_t)b * PIXPAD + p0 + r) * CIN + cg + cp * 2] =
            f2bf(t[r][cp * 2], t[r][cp * 2 + 1]);
    }
}

// ---------------------------------------------------------------------------
// Tensor-core GEMM with ldmatrix frag loads. 64(o) x 64(pix), K=128 resident.
// ---------------------------------------------------------------------------
__global__ __launch_bounds__(256) void gemm_mma_kernel(const float* __restrict__ bias) {
    int b    = blockIdx.z;
    int p0   = blockIdx.x * 64;
    int o0   = blockIdx.y * 64;

    __shared__ __align__(16) __nv_bfloat16 Asm[64][136];
    __shared__ __align__(16) __nv_bfloat16 Bsm[64][136];

    int tid = threadIdx.x;
#pragma unroll
    for (int i = 0; i < 4; i++) {
        int id = tid + i * 256;
        int r = id >> 4, c16 = id & 15;
        *(uint4*)&Asm[r][c16 * 8] =
            *(const uint4*)&g_Wbf[(size_t)(o0 + r) * CIN + c16 * 8];
        *(uint4*)&Bsm[r][c16 * 8] =
            *(const uint4*)&g_Sbf[((size_t)b * PIXPAD + p0 + r) * CIN + c16 * 8];
    }
    __syncthreads();

    int w = tid >> 5, lane = tid & 31;
    int mo = (w & 3) * 16;
    int n0 = (w >> 2) * 32;
    int lr = lane >> 2;
    int lc = (lane & 3) * 2;

    uint32_t sA = (uint32_t)__cvta_generic_to_shared(&Asm[0][0]);
    uint32_t sB = (uint32_t)__cvta_generic_to_shared(&Bsm[0][0]);

    uint32_t aAddr = sA + (uint32_t)((mo + (lane & 15)) * 136 + ((lane >> 4) << 3)) * 2;
    int quad = lane >> 3, r8 = lane & 7;
    uint32_t bAddr0 = sB + (uint32_t)((n0 + ((quad >> 1) << 3) + r8) * 136
                                      + ((quad & 1) << 3)) * 2;
    uint32_t bAddr1 = bAddr0 + (uint32_t)(16 * 136) * 2;

    float acc[4][4];
#pragma unroll
    for (int t = 0; t < 4; t++)
#pragma unroll
        for (int j = 0; j < 4; j++) acc[t][j] = 0.f;

#pragma unroll
    for (int ks = 0; ks < 8; ks++) {
        uint32_t koff = (uint32_t)(ks * 16) * 2;
        uint32_t a0, a1, a2, a3;
        ldsm4(a0, a1, a2, a3, aAddr + koff);
        uint32_t b00, b01, b10, b11;
        ldsm4(b00, b01, b10, b11, bAddr0 + koff);
        mma16816(acc[0], a0, a1, a2, a3, b00, b01);
        mma16816(acc[1], a0, a1, a2, a3, b10, b11);
        uint32_t c00, c01, c10, c11;
        ldsm4(c00, c01, c10, c11, bAddr1 + koff);
        mma16816(acc[2], a0, a1, a2, a3, c00, c01);
        mma16816(acc[3], a0, a1, a2, a3, c10, c11);
    }

    int o_  = o0 + mo + lr;
    float bb0 = bias[o_];
    float bb1 = bias[o_ + 8];
    float* row0 = g_y33 + ((size_t)b * COUT + o_) * PITCH33;
    float* row1 = row0 + (size_t)8 * PITCH33;
#pragma unroll
    for (int t = 0; t < 4; t++) {
        int pix = p0 + n0 + t * 8 + lc;
        if (pix + 1 < PIX33) {
            *(float2*)&row0[pix] = make_float2(acc[t][0] + bb0, acc[t][1] + bb0);
            *(float2*)&row1[pix] = make_float2(acc[t][2] + bb1, acc[t][3] + bb1);
        } else {
            if (pix < PIX33)     { row0[pix]     = acc[t][0] + bb0; row1[pix]     = acc[t][2] + bb1; }
            if (pix + 1 < PIX33) { row0[pix + 1] = acc[t][1] + bb0; row1[pix + 1] = acc[t][3] + bb1; }
        }
    }
}

// ---------------------------------------------------------------------------
// pi partial v4: y33 taps staged in SMEM. 64 pixels x 192 channels per block
// (2 phases of 96 channels). Each tile needs <=3 rows of the 33-grid.
// ---------------------------------------------------------------------------
__global__ __launch_bounds__(256) void pi_partial_kernel(const float* __restrict__ t_out) {
    int b     = blockIdx.y;
    int slice = blockIdx.z;
    int tx = threadIdx.x, ty = threadIdx.y;
    int tid = ty * 32 + tx;
    int p0 = blockIdx.x * 64;
    int pA = p0 + tx;
    int pB = pA + 32;
    int ppA = min(pA, PIX65 - 1);
    int ppB = min(pB, PIX65 - 1);

    int r_base = (p0 / 65) >> 1;

    // pixel A interp constants (local row indices into the 3-row stage)
    int yA = ppA / 65, xA = ppA - yA * 65;
    int y0A = yA >> 1, x0A = xA >> 1;
    int x1A = min(x0A + 1, 32);
    int ly0A = y0A - r_base;
    int ly1A = min(y0A + 1, 32) - r_base;
    float wyA = (yA & 1) * 0.5f, wxA = (xA & 1) * 0.5f;
    float a00 = (1.f - wyA) * (1.f - wxA), a01 = (1.f - wyA) * wxA;
    float a10 = wyA * (1.f - wxA),         a11 = wyA * wxA;
    int iA00 = ly0A * 33 + x0A, iA01 = ly0A * 33 + x1A;
    int iA10 = ly1A * 33 + x0A, iA11 = ly1A * 33 + x1A;

    // pixel B
    int yB = ppB / 65, xB = ppB - yB * 65;
    int y0B = yB >> 1, x0B = xB >> 1;
    int x1B = min(x0B + 1, 32);
    int ly0B = y0B - r_base;
    int ly1B = min(y0B + 1, 32) - r_base;
    float wyB = (yB & 1) * 0.5f, wxB = (xB & 1) * 0.5f;
    float b00 = (1.f - wyB) * (1.f - wxB), b01 = (1.f - wyB) * wxB;
    float b10 = wyB * (1.f - wxB),         b11 = wyB * wxB;
    int iB00 = ly0B * 33 + x0B, iB01 = ly0B * 33 + x1B;
    int iB10 = ly1B * 33 + x0B, iB11 = ly1B * 33 + x1B;

    __shared__ float stage[96 * 99];            // 96 channels x 3 rows x 33 cols
    __shared__ float r1[8][64], r2[8][64], r3[8][64], rs[8][64];

    float S1a = 0.f, S2a = 0.f, S3a = 0.f, Ssa = 0.f;
    float S1b = 0.f, S2b = 0.f, S3b = 0.f, Ssb = 0.f;

    for (int phase = 0; phase < 2; phase++) {
        __syncthreads();
        int chBase = slice * 192 + phase * 96;
        const float* ybase = g_y33 + ((size_t)b * COUT + chBase) * PITCH33;
        for (int e = tid; e < 96 * 99; e += 256) {
            int ch  = e / 99;
            int rem = e - ch * 99;
            int lrw = rem / 33;
            int col = rem - lrw * 33;
            int r   = min(r_base + lrw, 32);
            stage[e] = ybase[(size_t)ch * PITCH33 + r * 33 + col];
        }
        __syncthreads();

        const float* tpA = t_out + (size_t)b * COUT * PIX65
                         + (size_t)(chBase + ty) * PIX65 + ppA;
        const float* tpB = tpA + (ppB - ppA);
        const float* Tb  = stage + ty * 99;

        for (int k = 0; k < 2; k++) {
#pragma unroll
            for (int u = 0; u < 6; u++) {
                const float* T  = Tb + (u * 8) * 99;
                float ztA = tpA[(size_t)(u * 8) * PIX65];
                float ztB = tpB[(size_t)(u * 8) * PIX65];
                float zsA = a00 * T[iA00] + a01 * T[iA01]
                          + a10 * T[iA10] + a11 * T[iA11];
                float zsB = b00 * T[iB00] + b01 * T[iB01]
                          + b10 * T[iB10] + b11 * T[iB11];
                float eA = __expf(ztA);
                float eB = __expf(ztB);
                S1a += eA;        S1b += eB;
                S2a += ztA * eA;  S2b += ztB * eB;
                S3a += zsA * eA;  S3b += zsB * eB;
                Ssa += __expf(zsA);
                Ssb += __expf(zsB);
            }
            tpA += (size_t)48 * PIX65;
            tpB += (size_t)48 * PIX65;
            Tb  += 48 * 99;
        }
    }

    r1[ty][tx] = S1a; r1[ty][tx + 32] = S1b;
    r2[ty][tx] = S2a; r2[ty][tx + 32] = S2b;
    r3[ty][tx] = S3a; r3[ty][tx + 32] = S3b;
    rs[ty][tx] = Ssa; rs[ty][tx + 32] = Ssb;
    __syncthreads();

    if (ty < 2) {
        int col = ty * 32 + tx;
        int p   = p0 + col;
        if (p < PIX65) {
            float S1 = 0.f, S2 = 0.f, S3 = 0.f, Ss = 0.f;
#pragma unroll
            for (int u = 0; u < 8; u++) {
                S1 += r1[u][col]; S2 += r2[u][col];
                S3 += r3[u][col]; Ss += rs[u][col];
            }
            g_part[slice][b][0][p] = S1;
            g_part[slice][b][1][p] = S2;
            g_part[slice][b][2][p] = S3;
            g_part[slice][b][3][p] = Ss;
        }
    }
}

__global__ void pi_final_kernel() {
    int b = blockIdx.y;
    int p = blockIdx.x * 256 + threadIdx.x;
    float v = 0.f;
    if (p < PIX65) {
        float S1 = 0.f, S2 = 0.f, S3 = 0.f, Ss = 0.f;
#pragma unroll
        for (int s = 0; s < NSLICE; s++) {
            S1 += g_part[s][b][0][p];
            S2 += g_part[s][b][1][p];
            S3 += g_part[s][b][2][p];
            Ss += g_part[s][b][3][p];
        }
        float inv = 1.f / S1;
        v = S2 * inv - logf(S1) - S3 * inv + logf(Ss);
    }
    __shared__ float red[256];
    int tid = threadIdx.x;
    red[tid] = v;
    __syncthreads();
    for (int o = 128; o; o >>= 1) {
        if (tid < o) red[tid] += red[tid + o];
        __syncthreads();
    }
    if (tid == 0) atomicAdd(&g_pi, (double)red[0]);
}

// ---------------------------------------------------------------------------
// prep: ONE block per (side,row); direct double stores (no atomics).
// ---------------------------------------------------------------------------
__global__ __launch_bounds__(256) void prep_kernel(const float* __restrict__ t_logit,
                                                   const float* __restrict__ s_logit) {
    int side = blockIdx.x;            // 0=s, 1=t
    int row  = blockIdx.y;            // 0..151 (b*19+ch)
    int tid  = threadIdx.x;

    float d = 0.f, wz = 0.f;
    float* dst = (side ? g_Ut : g_Us) + (size_t)row * PIX129;

    if (side == 0) {
        const float* src = s_logit + (size_t)row * PIX129;
        for (int k = tid; k < PIX129; k += 256) {
            float z = src[k];
            float u = __expf(z);
            dst[k] = u;
            d += u; wz += u * z;
        }
    } else {
        const float* src = t_logit + (size_t)row * PIX65;
        for (int k = tid; k < PIX129; k += 256) {
            int y = k / 129, x = k - y * 129;
            int y0 = y >> 1, x0 = x >> 1;
            int y1 = min(y0 + 1, 64), x1 = min(x0 + 1, 64);
            float wy = (y & 1) * 0.5f, wx = (x & 1) * 0.5f;
            float top = (1.f - wx) * src[y0 * 65 + x0] + wx * src[y0 * 65 + x1];
            float bot = (1.f - wx) * src[y1 * 65 + x0] + wx * src[y1 * 65 + x1];
            float z = (1.f - wy) * top + wy * bot;
            float u = __expf(z);
            dst[k] = u;
            d += u; wz += u * z;
        }
    }

    __shared__ float rd[256], rw[256];
    rd[tid] = d; rw[tid] = wz;
    __syncthreads();
    for (int o = 128; o; o >>= 1) {
        if (tid < o) { rd[tid] += rd[tid + o]; rw[tid] += rw[tid + o]; }
        __syncthreads();
    }
    if (tid == 0) {
        g_d[side][row]  = (double)rd[0];
        g_Wz[side][row] = (double)rw[0];
    }
}

// ---------------------------------------------------------------------------
__global__ void gram_kernel() {
    int side = blockIdx.z;
    int b    = blockIdx.y;
    int k0   = blockIdx.x * 512;
    const float* U = (side ? g_Ut : g_Us) + (size_t)b * NCH * PIX129;

    __shared__ __align__(8) float sm[NCH][514];
    int tid = threadIdx.x;
    for (int idx = tid; idx < NCH * 512; idx += 256) {
        int i = idx >> 9, kk = idx & 511;
        int k = k0 + kk;
        sm[i][kk] = (k < PIX129) ? U[(size_t)i * PIX129 + k] : 0.f;
    }
    __syncthreads();

    if (tid < 190) {
        int i = 0, t = tid;
        while (t >= NCH - i) { t -= NCH - i; i++; }
        int j = i + t;
        const u64* ri = (const u64*)&sm[i][0];
        const u64* rj = (const u64*)&sm[j][0];
        u64 acc2 = pack2(0.f, 0.f);
#pragma unroll 4
        for (int kk = 0; kk < 256; kk++) fma2(acc2, ri[kk], rj[kk]);
        float lo, hi;
        unpack2(lo, hi, acc2);
        atomicAdd(&g_R[side][b][tid], (double)(lo + hi));
    }
}

// ---------------------------------------------------------------------------
__global__ void finalize_kernel(float* __restrict__ out) {
    int tid = threadIdx.x;
    __shared__ double sE[2][NCH];
    __shared__ double sG[2][361];
    __shared__ double sS[2][361];
    __shared__ double sN[2][NCH];
    __shared__ double red[512];

    if (tid < 2 * NCH) {
        int side = tid / NCH, i = tid % NCH;
        double e = 0.0;
        for (int b = 0; b < NB; b++) {
            double d = g_d[side][b * NCH + i];
            e += g_Wz[side][b * NCH + i] / d - log(d);
        }
        sE[side][i] = e;
    }
    if (tid < 361) {
        int i = tid / NCH, j = tid % NCH;
        int mi = min(i, j), mj = max(i, j);
        int p = mi * NCH - mi * (mi - 1) / 2 + (mj - mi);
        for (int side = 0; side < 2; side++) {
            double g = 0.0;
            for (int b = 0; b < NB; b++)
                g += g_R[side][b][p] /
                     (g_d[side][b * NCH + i] * g_d[side][b * NCH + j]);
            sG[side][tid] = g;
        }
    }
    __syncthreads();
    if (tid < 361) {
        int i = tid / NCH, j = tid % NCH;
        int mx = max(i, j);
        sS[0][tid] = (sE[0][mx] - sG[0][tid]) / (double)NB;
        sS[1][tid] = (sE[1][mx] - sG[1][tid]) / (double)NB;
    }
    __syncthreads();
    if (tid < 2 * NCH) {
        int side = tid / NCH, i = tid % NCH;
        double s = 0.0;
        for (int j = 0; j < NCH; j++) {
            double v = sS[side][i * NCH + j];
            s += v * v;
        }
        double n = sqrt(s);
        sN[side][i] = (n > 1e-12) ? n : 1e-12;
    }
    __syncthreads();
    double v = 0.0;
    if (tid < 361) {
        int i = tid / NCH;
        double dd = sS[0][tid] / sN[0][i] - sS[1][tid] / sN[1][i];
        v = dd * dd;
    }
    red[tid] = v;
    __syncthreads();
    for (int o = 256; o; o >>= 1) {
        if (tid < o) red[tid] += red[tid + o];
        __syncthreads();
    }
    if (tid == 0) {
        out[0] = (float)(g_pi / 25958400.0);
        out[1] = (float)red[0];
    }
}

// ---------------------------------------------------------------------------
extern "C" void kernel_launch(void* const* d_in, const int* in_sizes, int n_in,
                              void* d_out, int out_size) {
    const float *ptr[6] = {nullptr, nullptr, nullptr, nullptr, nullptr, nullptr};
    const int want[6] = {1115136, 25958400, 642200, 2529912, 98304, 768};

    for (int i = 0; i < n_in; i++) {
        long long s = in_sizes[i];
        for (int k = 0; k < 6; k++) {
            if (s == (long long)want[k] || s == 4LL * want[k]) {
                if (!ptr[k]) ptr[k] = (const float*)d_in[i];
            }
        }
    }
    if (n_in >= 6) {
        for (int k = 0; k < 6; k++)
            if (!ptr[k]) ptr[k] = (const float*)d_in[k];
    }

    const float* s_out   = ptr[0];
    const float* t_out   = ptr[1];
    const float* t_logit = ptr[2];
    const float* s_logit = ptr[3];
    const float* conv_w  = ptr[4];
    const float* conv_b  = ptr[5];

    zero_kernel<<<12, 256>>>();
    cudaEventRecord(g_e1, 0);
    cudaStreamWaitEvent(g_s2, g_e1, 0);

    // Chain 1 (default stream): bf16 prep (+W convert) + tensor GEMM + pi path.
    sbf_kernel<<<dim3(18, NB, 4), 256>>>(s_out, conv_w);
    gemm_mma_kernel<<<dim3(18, 12, NB), 256>>>(conv_b);
    pi_partial_kernel<<<dim3(67, NB, NSLICE), dim3(32, 8)>>>(t_out);
    pi_final_kernel<<<dim3((PIX65 + 255) / 256, NB), 256>>>();

    // Chain 2 (side stream): lo path.
    prep_kernel<<<dim3(2, NB * NCH), 256, 0, g_s2>>>(t_logit, s_logit);
    gram_kernel<<<dim3((PIX129 + 511) / 512, NB, 2), 256, 0, g_s2>>>();

    cudaEventRecord(g_e2, g_s2);
    cudaStreamWaitEvent(0, g_e2, 0);
    finalize_kernel<<<1, 512>>>((float*)d_out);
}

// round 15
// speedup vs baseline: 1.4020x; 1.4020x over previous
#include <cuda_runtime.h>
#include <cuda_bf16.h>
#include <cstdint>
#include <math.h>

// ---------------------------------------------------------------------------
#define PIX33 1089
#define PITCH33 1092
#define PIXPAD 1152
#define PIX65 4225
#define PIX129 16641
#define CIN 128
#define COUT 768
#define NB 8
#define NCH 19
#define NSLICE 4

typedef unsigned long long u64;

__device__ __forceinline__ u64 pack2(float lo, float hi) {
    u64 r; asm("mov.b64 %0, {%1, %2};" : "=l"(r) : "f"(lo), "f"(hi)); return r;
}
__device__ __forceinline__ void unpack2(float& lo, float& hi, u64 v) {
    asm("mov.b64 {%0, %1}, %2;" : "=f"(lo), "=f"(hi) : "l"(v));
}
__device__ __forceinline__ void fma2(u64& d, u64 a, u64 b) {
    asm("fma.rn.f32x2 %0, %1, %2, %3;" : "=l"(d) : "l"(a), "l"(b), "l"(d));
}
__device__ __forceinline__ void mma16816(float* c, uint32_t a0, uint32_t a1,
                                         uint32_t a2, uint32_t a3,
                                         uint32_t b0, uint32_t b1) {
    asm volatile(
        "mma.sync.aligned.m16n8k16.row.col.f32.bf16.bf16.f32 "
        "{%0,%1,%2,%3}, {%4,%5,%6,%7}, {%8,%9}, {%0,%1,%2,%3};"
        : "+f"(c[0]), "+f"(c[1]), "+f"(c[2]), "+f"(c[3])
        : "r"(a0), "r"(a1), "r"(a2), "r"(a3), "r"(b0), "r"(b1));
}
__device__ __forceinline__ void ldsm4(uint32_t& r0, uint32_t& r1,
                                      uint32_t& r2, uint32_t& r3, uint32_t addr) {
    asm volatile("ldmatrix.sync.aligned.m8n8.x4.shared.b16 {%0,%1,%2,%3}, [%4];"
                 : "=r"(r0), "=r"(r1), "=r"(r2), "=r"(r3) : "r"(addr));
}
__device__ __forceinline__ uint32_t f2bf(float a, float b) {
    __nv_bfloat162 h = __floats2bfloat162_rn(a, b);
    return *(uint32_t*)&h;
}

__device__ __align__(16) __nv_bfloat16 g_Wbf[COUT * CIN];        // [o][k]
__device__ __align__(16) __nv_bfloat16 g_Sbf[NB * PIXPAD * CIN]; // [b][pix][k]
__device__ __align__(16) float g_y33[NB * COUT * PITCH33];
__device__ __align__(16) float g_Ut[NB * NCH * PIX129];
__device__ __align__(16) float g_Us[NB * NCH * PIX129];
__device__ __align__(16) float g_part[NSLICE][NB][4][PIX65];
__device__ double g_pi;
__device__ double g_d[2][NB * NCH];
__device__ double g_Wz[2][NB * NCH];
__device__ double g_R[2][NB][190];

static cudaStream_t g_s2;
static cudaEvent_t g_e1, g_e2;
namespace {
struct StreamInit {
    StreamInit() {
        cudaStreamCreateWithFlags(&g_s2, cudaStreamNonBlocking);
        cudaEventCreateWithFlags(&g_e1, cudaEventDisableTiming);
        cudaEventCreateWithFlags(&g_e2, cudaEventDisableTiming);
    }
};
static StreamInit g_si;
}

// ---------------------------------------------------------------------------
// sbf: s_out fp32 [b][c][pix] -> bf16 transposed [b][pix][c], 32 ch/block.
// b==0 blocks additionally convert W AND zero g_pi / g_R (replaces zero_kernel).
// ---------------------------------------------------------------------------
__global__ __launch_bounds__(256) void sbf_kernel(const float* __restrict__ s_out,
                                                  const float* __restrict__ conv_w) {
    __shared__ float t[64][33];
    int b = blockIdx.y, p0 = blockIdx.x * 64, cg = blockIdx.z * 32;
    int tid = threadIdx.x;

    if (b == 0) {
        int flat = blockIdx.x * 4 + blockIdx.z;     // 0..71
        for (int idx = flat * 256 + tid; idx < COUT * CIN; idx += 72 * 256)
            g_Wbf[idx] = __float2bfloat16(conv_w[idx]);
        int zi = flat * 256 + tid;
        if (zi < 2 * NB * 190) ((double*)g_R)[zi] = 0.0;
        if (zi == 0) g_pi = 0.0;
    }

    int px = tid & 63, c4 = tid >> 6;
    const float* base = s_out + (size_t)b * CIN * PIX33;
#pragma unroll
    for (int c0 = 0; c0 < 32; c0 += 4) {
        int c = c0 + c4;
        int pix = p0 + px;
        t[px][c] = (pix < PIX33) ? base[(size_t)(cg + c) * PIX33 + pix] : 0.f;
    }
    __syncthreads();
#pragma unroll
    for (int i = 0; i < 4; i++) {
        int id = tid + i * 256;
        int r = id >> 4, cp = id & 15;
        *(uint32_t*)&g_Sbf[((size_t)b * PIXPAD + p0 + r) * CIN + cg + cp * 2] =
            f2bf(t[r][cp * 2], t[r][cp * 2 + 1]);
    }
}

// ---------------------------------------------------------------------------
// Tensor-core GEMM, double o-chunk per block: Bsm loaded once, 2x(Asm+MMA+epi).
// ---------------------------------------------------------------------------
__global__ __launch_bounds__(256) void gemm_mma_kernel(const float* __restrict__ bias) {
    int b    = blockIdx.z;
    int p0   = blockIdx.x * 64;
    int obase = blockIdx.y * 128;

    __shared__ __align__(16) __nv_bfloat16 Asm[64][136];
    __shared__ __align__(16) __nv_bfloat16 Bsm[64][136];

    int tid = threadIdx.x;
    // Load B (pixel) tile once.
#pragma unroll
    for (int i = 0; i < 4; i++) {
        int id = tid + i * 256;
        int r = id >> 4, c16 = id & 15;
        *(uint4*)&Bsm[r][c16 * 8] =
            *(const uint4*)&g_Sbf[((size_t)b * PIXPAD + p0 + r) * CIN + c16 * 8];
    }

    int w = tid >> 5, lane = tid & 31;
    int mo = (w & 3) * 16;
    int n0 = (w >> 2) * 32;
    int lr = lane >> 2;
    int lc = (lane & 3) * 2;

    uint32_t sA = (uint32_t)__cvta_generic_to_shared(&Asm[0][0]);
    uint32_t sB = (uint32_t)__cvta_generic_to_shared(&Bsm[0][0]);

    uint32_t aAddr = sA + (uint32_t)((mo + (lane & 15)) * 136 + ((lane >> 4) << 3)) * 2;
    int quad = lane >> 3, r8 = lane & 7;
    uint32_t bAddr0 = sB + (uint32_t)((n0 + ((quad >> 1) << 3) + r8) * 136
                                      + ((quad & 1) << 3)) * 2;
    uint32_t bAddr1 = bAddr0 + (uint32_t)(16 * 136) * 2;

    for (int oc = 0; oc < 2; oc++) {
        int o0 = obase + oc * 64;
        // Load A (W) chunk.
#pragma unroll
        for (int i = 0; i < 4; i++) {
            int id = tid + i * 256;
            int r = id >> 4, c16 = id & 15;
            *(uint4*)&Asm[r][c16 * 8] =
                *(const uint4*)&g_Wbf[(size_t)(o0 + r) * CIN + c16 * 8];
        }
        __syncthreads();

        float acc[4][4];
#pragma unroll
        for (int t = 0; t < 4; t++)
#pragma unroll
            for (int j = 0; j < 4; j++) acc[t][j] = 0.f;

#pragma unroll
        for (int ks = 0; ks < 8; ks++) {
            uint32_t koff = (uint32_t)(ks * 16) * 2;
            uint32_t a0, a1, a2, a3;
            ldsm4(a0, a1, a2, a3, aAddr + koff);
            uint32_t b00, b01, b10, b11;
            ldsm4(b00, b01, b10, b11, bAddr0 + koff);
            mma16816(acc[0], a0, a1, a2, a3, b00, b01);
            mma16816(acc[1], a0, a1, a2, a3, b10, b11);
            uint32_t c00, c01, c10, c11;
            ldsm4(c00, c01, c10, c11, bAddr1 + koff);
            mma16816(acc[2], a0, a1, a2, a3, c00, c01);
            mma16816(acc[3], a0, a1, a2, a3, c10, c11);
        }

        int o_  = o0 + mo + lr;
        float bb0 = bias[o_];
        float bb1 = bias[o_ + 8];
        float* row0 = g_y33 + ((size_t)b * COUT + o_) * PITCH33;
        float* row1 = row0 + (size_t)8 * PITCH33;
#pragma unroll
        for (int t = 0; t < 4; t++) {
            int pix = p0 + n0 + t * 8 + lc;
            if (pix + 1 < PIX33) {
                *(float2*)&row0[pix] = make_float2(acc[t][0] + bb0, acc[t][1] + bb0);
                *(float2*)&row1[pix] = make_float2(acc[t][2] + bb1, acc[t][3] + bb1);
            } else {
                if (pix < PIX33)     { row0[pix]     = acc[t][0] + bb0; row1[pix]     = acc[t][2] + bb1; }
                if (pix + 1 < PIX33) { row0[pix + 1] = acc[t][1] + bb0; row1[pix + 1] = acc[t][3] + bb1; }
            }
        }
        if (oc == 0) __syncthreads();   // protect Asm before reload
    }
}

// ---------------------------------------------------------------------------
// pi partial — R7/R13-measured config (unchanged, 50us).
// ---------------------------------------------------------------------------
__global__ __launch_bounds__(256) void pi_partial_kernel(const float* __restrict__ t_out) {
    int b     = blockIdx.y;
    int slice = blockIdx.z;
    int tx = threadIdx.x, ty = threadIdx.y;
    int pA = blockIdx.x * 64 + tx;
    int pB = pA + 32;
    int ppA = (pA < PIX65) ? pA : 0;
    int ppB = (pB < PIX65) ? pB : 0;

    int yA = ppA / 65, xA = ppA - yA * 65;
    int y0A = yA >> 1, x0A = xA >> 1;
    int y1A = min(y0A + 1, 32), x1A = min(x0A + 1, 32);
    float wyA = (yA & 1) * 0.5f, wxA = (xA & 1) * 0.5f;
    float a00 = (1.f - wyA) * (1.f - wxA), a01 = (1.f - wyA) * wxA;
    float a10 = wyA * (1.f - wxA),         a11 = wyA * wxA;
    int iA00 = y0A * 33 + x0A, iA01 = y0A * 33 + x1A;
    int iA10 = y1A * 33 + x0A, iA11 = y1A * 33 + x1A;

    int yB = ppB / 65, xB = ppB - yB * 65;
    int y0B = yB >> 1, x0B = xB >> 1;
    int y1B = min(y0B + 1, 32), x1B = min(x0B + 1, 32);
    float wyB = (yB & 1) * 0.5f, wxB = (xB & 1) * 0.5f;
    float b00 = (1.f - wyB) * (1.f - wxB), b01 = (1.f - wyB) * wxB;
    float b10 = wyB * (1.f - wxB),         b11 = wyB * wxB;
    int iB00 = y0B * 33 + x0B, iB01 = y0B * 33 + x1B;
    int iB10 = y1B * 33 + x0B, iB11 = y1B * 33 + x1B;

    const float* tpA = t_out + (size_t)b * COUT * PIX65
                     + (size_t)(slice * 192 + ty) * PIX65 + ppA;
    const float* tpB = t_out + (size_t)b * COUT * PIX65
                     + (size_t)(slice * 192 + ty) * PIX65 + ppB;
    const float* yp  = g_y33 + ((size_t)b * COUT + slice * 192 + ty) * PITCH33;

    float S1a = 0.f, S2a = 0.f, S3a = 0.f, Ssa = 0.f;
    float S1b = 0.f, S2b = 0.f, S3b = 0.f, Ssb = 0.f;

    for (int k = 0; k < 6; k++) {
#pragma unroll
        for (int u = 0; u < 4; u++) {
            const float* Y  = yp + (size_t)(u * 8) * PITCH33;
            float ztA = tpA[(size_t)(u * 8) * PIX65];
            float ztB = tpB[(size_t)(u * 8) * PIX65];
            float zsA = a00 * Y[iA00] + a01 * Y[iA01]
                      + a10 * Y[iA10] + a11 * Y[iA11];
            float zsB = b00 * Y[iB00] + b01 * Y[iB01]
                      + b10 * Y[iB10] + b11 * Y[iB11];
            float eA = __expf(ztA);
            float eB = __expf(ztB);
            S1a += eA;        S1b += eB;
            S2a += ztA * eA;  S2b += ztB * eB;
            S3a += zsA * eA;  S3b += zsB * eB;
            Ssa += __expf(zsA);
            Ssb += __expf(zsB);
        }
        tpA += (size_t)32 * PIX65;
        tpB += (size_t)32 * PIX65;
        yp  += (size_t)32 * PITCH33;
    }

    __shared__ float r1[8][64], r2[8][64], r3[8][64], rs[8][64];
    r1[ty][tx] = S1a; r1[ty][tx + 32] = S1b;
    r2[ty][tx] = S2a; r2[ty][tx + 32] = S2b;
    r3[ty][tx] = S3a; r3[ty][tx + 32] = S3b;
    rs[ty][tx] = Ssa; rs[ty][tx + 32] = Ssb;
    __syncthreads();

    if (ty < 2) {
        int col = ty * 32 + tx;
        int p   = blockIdx.x * 64 + col;
        if (p < PIX65) {
            float S1 = 0.f, S2 = 0.f, S3 = 0.f, Ss = 0.f;
#pragma unroll
            for (int u = 0; u < 8; u++) {
                S1 += r1[u][col]; S2 += r2[u][col];
                S3 += r3[u][col]; Ss += rs[u][col];
            }
            g_part[slice][b][0][p] = S1;
            g_part[slice][b][1][p] = S2;
            g_part[slice][b][2][p] = S3;
            g_part[slice][b][3][p] = Ss;
        }
    }
}

__global__ void pi_final_kernel() {
    int b = blockIdx.y;
    int p = blockIdx.x * 256 + threadIdx.x;
    float v = 0.f;
    if (p < PIX65) {
        float S1 = 0.f, S2 = 0.f, S3 = 0.f, Ss = 0.f;
#pragma unroll
        for (int s = 0; s < NSLICE; s++) {
            S1 += g_part[s][b][0][p];
            S2 += g_part[s][b][1][p];
            S3 += g_part[s][b][2][p];
            Ss += g_part[s][b][3][p];
        }
        float inv = 1.f / S1;
        v = S2 * inv - logf(S1) - S3 * inv + logf(Ss);
    }
    __shared__ float red[256];
    int tid = threadIdx.x;
    red[tid] = v;
    __syncthreads();
    for (int o = 128; o; o >>= 1) {
        if (tid < o) red[tid] += red[tid + o];
        __syncthreads();
    }
    if (tid == 0) atomicAdd(&g_pi, (double)red[0]);
}

// ---------------------------------------------------------------------------
// prep: ONE block per (side,row); direct double stores (no atomics).
// ---------------------------------------------------------------------------
__global__ __launch_bounds__(256) void prep_kernel(const float* __restrict__ t_logit,
                                                   const float* __restrict__ s_logit) {
    int side = blockIdx.x;            // 0=s, 1=t
    int row  = blockIdx.y;            // 0..151 (b*19+ch)
    int tid  = threadIdx.x;

    float d = 0.f, wz = 0.f;
    float* dst = (side ? g_Ut : g_Us) + (size_t)row * PIX129;

    if (side == 0) {
        const float* src = s_logit + (size_t)row * PIX129;
        for (int k = tid; k < PIX129; k += 256) {
            float z = src[k];
            float u = __expf(z);
            dst[k] = u;
            d += u; wz += u * z;
        }
    } else {
        const float* src = t_logit + (size_t)row * PIX65;
        for (int k = tid; k < PIX129; k += 256) {
            int y = k / 129, x = k - y * 129;
            int y0 = y >> 1, x0 = x >> 1;
            int y1 = min(y0 + 1, 64), x1 = min(x0 + 1, 64);
            float wy = (y & 1) * 0.5f, wx = (x & 1) * 0.5f;
            float top = (1.f - wx) * src[y0 * 65 + x0] + wx * src[y0 * 65 + x1];
            float bot = (1.f - wx) * src[y1 * 65 + x0] + wx * src[y1 * 65 + x1];
            float z = (1.f - wy) * top + wy * bot;
            float u = __expf(z);
            dst[k] = u;
            d += u; wz += u * z;
        }
    }

    __shared__ float rd[256], rw[256];
    rd[tid] = d; rw[tid] = wz;
    __syncthreads();
    for (int o = 128; o; o >>= 1) {
        if (tid < o) { rd[tid] += rd[tid + o]; rw[tid] += rw[tid + o]; }
        __syncthreads();
    }
    if (tid == 0) {
        g_d[side][row]  = (double)rd[0];
        g_Wz[side][row] = (double)rw[0];
    }
}

// ---------------------------------------------------------------------------
__global__ void gram_kernel() {
    int side = blockIdx.z;
    int b    = blockIdx.y;
    int k0   = blockIdx.x * 512;
    const float* U = (side ? g_Ut : g_Us) + (size_t)b * NCH * PIX129;

    __shared__ __align__(8) float sm[NCH][514];
    int tid = threadIdx.x;
    for (int idx = tid; idx < NCH * 512; idx += 256) {
        int i = idx >> 9, kk = idx & 511;
        int k = k0 + kk;
        sm[i][kk] = (k < PIX129) ? U[(size_t)i * PIX129 + k] : 0.f;
    }
    __syncthreads();

    if (tid < 190) {
        int i = 0, t = tid;
        while (t >= NCH - i) { t -= NCH - i; i++; }
        int j = i + t;
        const u64* ri = (const u64*)&sm[i][0];
        const u64* rj = (const u64*)&sm[j][0];
        u64 acc2 = pack2(0.f, 0.f);
#pragma unroll 4
        for (int kk = 0; kk < 256; kk++) fma2(acc2, ri[kk], rj[kk]);
        float lo, hi;
        unpack2(lo, hi, acc2);
        atomicAdd(&g_R[side][b][tid], (double)(lo + hi));
    }
}

// ---------------------------------------------------------------------------
__global__ void finalize_kernel(float* __restrict__ out) {
    int tid = threadIdx.x;
    __shared__ double sE[2][NCH];
    __shared__ double sG[2][361];
    __shared__ double sS[2][361];
    __shared__ double sN[2][NCH];
    __shared__ double red[512];

    if (tid < 2 * NCH) {
        int side = tid / NCH, i = tid % NCH;
        double e = 0.0;
        for (int b = 0; b < NB; b++) {
            double d = g_d[side][b * NCH + i];
            e += g_Wz[side][b * NCH + i] / d - log(d);
        }
        sE[side][i] = e;
    }
    if (tid < 361) {
        int i = tid / NCH, j = tid % NCH;
        int mi = min(i, j), mj = max(i, j);
        int p = mi * NCH - mi * (mi - 1) / 2 + (mj - mi);
        for (int side = 0; side < 2; side++) {
            double g = 0.0;
            for (int b = 0; b < NB; b++)
                g += g_R[side][b][p] /
                     (g_d[side][b * NCH + i] * g_d[side][b * NCH + j]);
            sG[side][tid] = g;
        }
    }
    __syncthreads();
    if (tid < 361) {
        int i = tid / NCH, j = tid % NCH;
        int mx = max(i, j);
        sS[0][tid] = (sE[0][mx] - sG[0][tid]) / (double)NB;
        sS[1][tid] = (sE[1][mx] - sG[1][tid]) / (double)NB;
    }
    __syncthreads();
    if (tid < 2 * NCH) {
        int side = tid / NCH, i = tid % NCH;
        double s = 0.0;
        for (int j = 0; j < NCH; j++) {
            double v = sS[side][i * NCH + j];
            s += v * v;
        }
        double n = sqrt(s);
        sN[side][i] = (n > 1e-12) ? n : 1e-12;
    }
    __syncthreads();
    double v = 0.0;
    if (tid < 361) {
        int i = tid / NCH;
        double dd = sS[0][tid] / sN[0][i] - sS[1][tid] / sN[1][i];
        v = dd * dd;
    }
    red[tid] = v;
    __syncthreads();
    for (int o = 256; o; o >>= 1) {
        if (tid < o) red[tid] += red[tid + o];
        __syncthreads();
    }
    if (tid == 0) {
        out[0] = (float)(g_pi / 25958400.0);
        out[1] = (float)red[0];
    }
}

// ---------------------------------------------------------------------------
extern "C" void kernel_launch(void* const* d_in, const int* in_sizes, int n_in,
                              void* d_out, int out_size) {
    const float *ptr[6] = {nullptr, nullptr, nullptr, nullptr, nullptr, nullptr};
    const int want[6] = {1115136, 25958400, 642200, 2529912, 98304, 768};

    for (int i = 0; i < n_in; i++) {
        long long s = in_sizes[i];
        for (int k = 0; k < 6; k++) {
            if (s == (long long)want[k] || s == 4LL * want[k]) {
                if (!ptr[k]) ptr[k] = (const float*)d_in[i];
            }
        }
    }
    if (n_in >= 6) {
        for (int k = 0; k < 6; k++)
            if (!ptr[k]) ptr[k] = (const float*)d_in[k];
    }

    const float* s_out   = ptr[0];
    const float* t_out   = ptr[1];
    const float* t_logit = ptr[2];
    const float* s_logit = ptr[3];
    const float* conv_w  = ptr[4];
    const float* conv_b  = ptr[5];

    // Main stream: sbf (includes W convert + accumulator zeroing) -> fork.
    sbf_kernel<<<dim3(18, NB, 4), 256>>>(s_out, conv_w);
    cudaEventRecord(g_e1, 0);
    cudaStreamWaitEvent(g_s2, g_e1, 0);

    // Chain 1 (default stream): tensor GEMM + pi path.
    gemm_mma_kernel<<<dim3(18, 6, NB), 256>>>(conv_b);
    pi_partial_kernel<<<dim3(67, NB, NSLICE), dim3(32, 8)>>>(t_out);
    pi_final_kernel<<<dim3((PIX65 + 255) / 256, NB), 256>>>();

    // Chain 2 (side stream): lo path.
    prep_kernel<<<dim3(2, NB * NCH), 256, 0, g_s2>>>(t_logit, s_logit);
    gram_kernel<<<dim3((PIX129 + 511) / 512, NB, 2), 256, 0, g_s2>>>();

    cudaEventRecord(g_e2, g_s2);
    cudaStreamWaitEvent(0, g_e2, 0);
    finalize_kernel<<<1, 512>>>((float*)d_out);
}

// round 16
// speedup vs baseline: 1.4219x; 1.0142x over previous
#include <cuda_runtime.h>
#include <cuda_bf16.h>
#include <cstdint>
#include <math.h>

// ---------------------------------------------------------------------------
#define PIX33 1089
#define PITCH33 1092
#define PIXPAD 1152
#define PIX65 4225
#define PIX129 16641
#define CIN 128
#define COUT 768
#define NB 8
#define NCH 19
#define NSLICE 4

typedef unsigned long long u64;

__device__ __forceinline__ u64 pack2(float lo, float hi) {
    u64 r; asm("mov.b64 %0, {%1, %2};" : "=l"(r) : "f"(lo), "f"(hi)); return r;
}
__device__ __forceinline__ void unpack2(float& lo, float& hi, u64 v) {
    asm("mov.b64 {%0, %1}, %2;" : "=f"(lo), "=f"(hi) : "l"(v));
}
__device__ __forceinline__ void fma2(u64& d, u64 a, u64 b) {
    asm("fma.rn.f32x2 %0, %1, %2, %3;" : "=l"(d) : "l"(a), "l"(b), "l"(d));
}
__device__ __forceinline__ void mma16816(float* c, uint32_t a0, uint32_t a1,
                                         uint32_t a2, uint32_t a3,
                                         uint32_t b0, uint32_t b1) {
    asm volatile(
        "mma.sync.aligned.m16n8k16.row.col.f32.bf16.bf16.f32 "
        "{%0,%1,%2,%3}, {%4,%5,%6,%7}, {%8,%9}, {%0,%1,%2,%3};"
        : "+f"(c[0]), "+f"(c[1]), "+f"(c[2]), "+f"(c[3])
        : "r"(a0), "r"(a1), "r"(a2), "r"(a3), "r"(b0), "r"(b1));
}
__device__ __forceinline__ void ldsm4(uint32_t& r0, uint32_t& r1,
                                      uint32_t& r2, uint32_t& r3, uint32_t addr) {
    asm volatile("ldmatrix.sync.aligned.m8n8.x4.shared.b16 {%0,%1,%2,%3}, [%4];"
                 : "=r"(r0), "=r"(r1), "=r"(r2), "=r"(r3) : "r"(addr));
}
__device__ __forceinline__ uint32_t f2bf(float a, float b) {
    __nv_bfloat162 h = __floats2bfloat162_rn(a, b);
    return *(uint32_t*)&h;
}

__device__ __align__(16) __nv_bfloat16 g_Wbf[COUT * CIN];        // [o][k]
__device__ __align__(16) __nv_bfloat16 g_Sbf[NB * PIXPAD * CIN]; // [b][pix][k]
__device__ __align__(16) float g_y33[NB * COUT * PITCH33];
__device__ __align__(16) float g_Ut[NB * NCH * PIX129];
__device__ __align__(16) float g_Us[NB * NCH * PIX129];
__device__ __align__(16) float g_part[NSLICE][NB][4][PIX65];
__device__ double g_pi;
__device__ double g_d[2][NB * NCH];
__device__ double g_Wz[2][NB * NCH];
__device__ double g_R[2][NB][190];

static cudaStream_t g_s2;
static cudaEvent_t g_e1, g_e2;
namespace {
struct StreamInit {
    StreamInit() {
        cudaStreamCreateWithFlags(&g_s2, cudaStreamNonBlocking);
        cudaEventCreateWithFlags(&g_e1, cudaEventDisableTiming);
        cudaEventCreateWithFlags(&g_e2, cudaEventDisableTiming);
    }
};
static StreamInit g_si;
}

// ---------------------------------------------------------------------------
// sbf: s_out fp32 [b][c][pix] -> bf16 transposed [b][pix][c], 32 ch/block.
// b==0 blocks additionally convert W AND zero g_pi / g_R.
// ---------------------------------------------------------------------------
__global__ __launch_bounds__(256) void sbf_kernel(const float* __restrict__ s_out,
                                                  const float* __restrict__ conv_w) {
    __shared__ float t[64][33];
    int b = blockIdx.y, p0 = blockIdx.x * 64, cg = blockIdx.z * 32;
    int tid = threadIdx.x;

    if (b == 0) {
        int flat = blockIdx.x * 4 + blockIdx.z;     // 0..71
        for (int idx = flat * 256 + tid; idx < COUT * CIN; idx += 72 * 256)
            g_Wbf[idx] = __float2bfloat16(conv_w[idx]);
        int zi = flat * 256 + tid;
        if (zi < 2 * NB * 190) ((double*)g_R)[zi] = 0.0;
        if (zi == 0) g_pi = 0.0;
    }

    int px = tid & 63, c4 = tid >> 6;
    const float* base = s_out + (size_t)b * CIN * PIX33;
#pragma unroll
    for (int c0 = 0; c0 < 32; c0 += 4) {
        int c = c0 + c4;
        int pix = p0 + px;
        t[px][c] = (pix < PIX33) ? base[(size_t)(cg + c) * PIX33 + pix] : 0.f;
    }
    __syncthreads();
#pragma unroll
    for (int i = 0; i < 4; i++) {
        int id = tid + i * 256;
        int r = id >> 4, cp = id & 15;
        *(uint32_t*)&g_Sbf[((size_t)b * PIXPAD + p0 + r) * CIN + cg + cp * 2] =
            f2bf(t[r][cp * 2], t[r][cp * 2 + 1]);
    }
}

// ---------------------------------------------------------------------------
// Tensor-core GEMM, double o-chunk per block.
// ---------------------------------------------------------------------------
__global__ __launch_bounds__(256) void gemm_mma_kernel(const float* __restrict__ bias) {
    int b    = blockIdx.z;
    int p0   = blockIdx.x * 64;
    int obase = blockIdx.y * 128;

    __shared__ __align__(16) __nv_bfloat16 Asm[64][136];
    __shared__ __align__(16) __nv_bfloat16 Bsm[64][136];

    int tid = threadIdx.x;
#pragma unroll
    for (int i = 0; i < 4; i++) {
        int id = tid + i * 256;
        int r = id >> 4, c16 = id & 15;
        *(uint4*)&Bsm[r][c16 * 8] =
            *(const uint4*)&g_Sbf[((size_t)b * PIXPAD + p0 + r) * CIN + c16 * 8];
    }

    int w = tid >> 5, lane = tid & 31;
    int mo = (w & 3) * 16;
    int n0 = (w >> 2) * 32;
    int lr = lane >> 2;
    int lc = (lane & 3) * 2;

    uint32_t sA = (uint32_t)__cvta_generic_to_shared(&Asm[0][0]);
    uint32_t sB = (uint32_t)__cvta_generic_to_shared(&Bsm[0][0]);

    uint32_t aAddr = sA + (uint32_t)((mo + (lane & 15)) * 136 + ((lane >> 4) << 3)) * 2;
    int quad = lane >> 3, r8 = lane & 7;
    uint32_t bAddr0 = sB + (uint32_t)((n0 + ((quad >> 1) << 3) + r8) * 136
                                      + ((quad & 1) << 3)) * 2;
    uint32_t bAddr1 = bAddr0 + (uint32_t)(16 * 136) * 2;

    for (int oc = 0; oc < 2; oc++) {
        int o0 = obase + oc * 64;
#pragma unroll
        for (int i = 0; i < 4; i++) {
            int id = tid + i * 256;
            int r = id >> 4, c16 = id & 15;
            *(uint4*)&Asm[r][c16 * 8] =
                *(const uint4*)&g_Wbf[(size_t)(o0 + r) * CIN + c16 * 8];
        }
        __syncthreads();

        float acc[4][4];
#pragma unroll
        for (int t = 0; t < 4; t++)
#pragma unroll
            for (int j = 0; j < 4; j++) acc[t][j] = 0.f;

#pragma unroll
        for (int ks = 0; ks < 8; ks++) {
            uint32_t koff = (uint32_t)(ks * 16) * 2;
            uint32_t a0, a1, a2, a3;
            ldsm4(a0, a1, a2, a3, aAddr + koff);
            uint32_t b00, b01, b10, b11;
            ldsm4(b00, b01, b10, b11, bAddr0 + koff);
            mma16816(acc[0], a0, a1, a2, a3, b00, b01);
            mma16816(acc[1], a0, a1, a2, a3, b10, b11);
            uint32_t c00, c01, c10, c11;
            ldsm4(c00, c01, c10, c11, bAddr1 + koff);
            mma16816(acc[2], a0, a1, a2, a3, c00, c01);
            mma16816(acc[3], a0, a1, a2, a3, c10, c11);
        }

        int o_  = o0 + mo + lr;
        float bb0 = bias[o_];
        float bb1 = bias[o_ + 8];
        float* row0 = g_y33 + ((size_t)b * COUT + o_) * PITCH33;
        float* row1 = row0 + (size_t)8 * PITCH33;
#pragma unroll
        for (int t = 0; t < 4; t++) {
            int pix = p0 + n0 + t * 8 + lc;
            if (pix + 1 < PIX33) {
                *(float2*)&row0[pix] = make_float2(acc[t][0] + bb0, acc[t][1] + bb0);
                *(float2*)&row1[pix] = make_float2(acc[t][2] + bb1, acc[t][3] + bb1);
            } else {
                if (pix < PIX33)     { row0[pix]     = acc[t][0] + bb0; row1[pix]     = acc[t][2] + bb1; }
                if (pix + 1 < PIX33) { row0[pix + 1] = acc[t][1] + bb0; row1[pix + 1] = acc[t][3] + bb1; }
            }
        }
        if (oc == 0) __syncthreads();
    }
}

// ---------------------------------------------------------------------------
// pi partial v5: vertical pixel pairing with shared y33 taps.
// bx < 64: main blocks — rows (2*r2, 2*r2+1), cols cc*32+tx of the 64x64
//   sub-grid; 4 shared taps per channel serve both pixels.
// bx >= 64: edge blocks — the 129 ragged pixels (row 64 + col 64), generic.
// ---------------------------------------------------------------------------
__global__ __launch_bounds__(256) void pi_partial_kernel(const float* __restrict__ t_out) {
    int b     = blockIdx.y;
    int slice = blockIdx.z;
    int tx = threadIdx.x, ty = threadIdx.y;
    int bx = blockIdx.x;

    __shared__ float r1[8][64], r2s[8][64], r3[8][64], rs[8][64];

    float S1a = 0.f, S2a = 0.f, S3a = 0.f, Ssa = 0.f;
    float S1b = 0.f, S2b = 0.f, S3b = 0.f, Ssb = 0.f;

    const float* tbase = t_out + (size_t)b * COUT * PIX65
                       + (size_t)(slice * 192 + ty) * PIX65;
    const float* yb = g_y33 + ((size_t)b * COUT + slice * 192 + ty) * PITCH33;

    int pOutA = 0, pOutB = 0;         // global pixel ids for the write phase
    bool vA = true, vB = true;

    if (bx < 64) {
        int r2 = bx >> 1;             // 0..31
        int cc = bx & 1;
        int x  = cc * 32 + tx;        // 0..63
        int x0 = x >> 1;
        int x1 = x0 + 1;              // x<=63 -> x0<=31 -> x1<=32, in range
        float wx = (x & 1) * 0.5f;
        float omwx = 1.f - wx;
        int o00 = r2 * 33 + x0, o01 = r2 * 33 + x1;
        int o10 = o00 + 33,     o11 = o01 + 33;

        pOutA = (2 * r2) * 65 + x;
        pOutB = pOutA + 65;

        const float* tpA = tbase + pOutA;
        const float* tpB = tbase + pOutB;
        const float* yp  = yb;

        for (int k = 0; k < 6; k++) {
#pragma unroll
            for (int u = 0; u < 4; u++) {
                const float* Y  = yp + (size_t)(u * 8) * PITCH33;
                float ztA = tpA[(size_t)(u * 8) * PIX65];
                float ztB = tpB[(size_t)(u * 8) * PIX65];
                float q00 = Y[o00], q01 = Y[o01];
                float q10 = Y[o10], q11 = Y[o11];
                float h0 = omwx * q00 + wx * q01;
                float h1 = omwx * q10 + wx * q11;
                float zsA = h0;
                float zsB = 0.5f * (h0 + h1);
                float eA = __expf(ztA);
                float eB = __expf(ztB);
                S1a += eA;        S1b += eB;
                S2a += ztA * eA;  S2b += ztB * eB;
                S3a += zsA * eA;  S3b += zsB * eB;
                Ssa += __expf(zsA);
                Ssb += __expf(zsB);
            }
            tpA += (size_t)32 * PIX65;
            tpB += (size_t)32 * PIX65;
            yp  += (size_t)32 * PITCH33;
        }
    } else {
        // Edge pixels: pidx in [0,129): row-64 (0..64), then col-64 (65..128).
        int eb = bx - 64;                     // 0..2
        int piA = eb * 64 + tx;
        int piB = piA + 32;
        vA = (piA < 129); vB = (piB < 129);
        int qA = vA ? piA : 0;
        int qB = vB ? piB : 0;
        pOutA = (qA < 65) ? (64 * 65 + qA) : ((qA - 65) * 65 + 64);
        pOutB = (qB < 65) ? (64 * 65 + qB) : ((qB - 65) * 65 + 64);

        // generic 4-tap constants per pixel
        int yA = pOutA / 65, xA = pOutA - yA * 65;
        int y0A = yA >> 1, x0A = xA >> 1;
        int y1A = min(y0A + 1, 32), x1A = min(x0A + 1, 32);
        float wyA = (yA & 1) * 0.5f, wxA = (xA & 1) * 0.5f;
        float a00 = (1.f - wyA) * (1.f - wxA), a01 = (1.f - wyA) * wxA;
        float a10 = wyA * (1.f - wxA),         a11 = wyA * wxA;
        int iA00 = y0A * 33 + x0A, iA01 = y0A * 33 + x1A;
        int iA10 = y1A * 33 + x0A, iA11 = y1A * 33 + x1A;

        int yB = pOutB / 65, xB = pOutB - yB * 65;
        int y0B = yB >> 1, x0B = xB >> 1;
        int y1B = min(y0B + 1, 32), x1B = min(x0B + 1, 32);
        float wyB = (yB & 1) * 0.5f, wxB = (xB & 1) * 0.5f;
        float b00 = (1.f - wyB) * (1.f - wxB), b01 = (1.f - wyB) * wxB;
        float b10 = wyB * (1.f - wxB),         b11 = wyB * wxB;
        int iB00 = y0B * 33 + x0B, iB01 = y0B * 33 + x1B;
        int iB10 = y1B * 33 + x0B, iB11 = y1B * 33 + x1B;

        const float* tpA = tbase + pOutA;
        const float* tpB = tbase + pOutB;
        const float* yp  = yb;

        for (int k = 0; k < 6; k++) {
#pragma unroll
            for (int u = 0; u < 4; u++) {
                const float* Y  = yp + (size_t)(u * 8) * PITCH33;
                float ztA = tpA[(size_t)(u * 8) * PIX65];
                float ztB = tpB[(size_t)(u * 8) * PIX65];
                float zsA = a00 * Y[iA00] + a01 * Y[iA01]
                          + a10 * Y[iA10] + a11 * Y[iA11];
                float zsB = b00 * Y[iB00] + b01 * Y[iB01]
                          + b10 * Y[iB10] + b11 * Y[iB11];
                float eA = __expf(ztA);
                float eB = __expf(ztB);
                S1a += eA;        S1b += eB;
                S2a += ztA * eA;  S2b += ztB * eB;
                S3a += zsA * eA;  S3b += zsB * eB;
                Ssa += __expf(zsA);
                Ssb += __expf(zsB);
            }
            tpA += (size_t)32 * PIX65;
            tpB += (size_t)32 * PIX65;
            yp  += (size_t)32 * PITCH33;
        }
    }

    r1[ty][tx] = S1a;  r1[ty][tx + 32] = S1b;
    r2s[ty][tx] = S2a; r2s[ty][tx + 32] = S2b;
    r3[ty][tx] = S3a;  r3[ty][tx + 32] = S3b;
    rs[ty][tx] = Ssa;  rs[ty][tx + 32] = Ssb;

    // share pixel ids / validity with the writer threads via SMEM
    __shared__ int pid[64];
    __shared__ unsigned char pvalid[64];
    if (ty == 0) { pid[tx] = pOutA; pvalid[tx] = vA; }
    if (ty == 1) { pid[tx + 32] = pOutB; pvalid[tx + 32] = vB; }
    __syncthreads();

    if (ty < 2) {
        int col = ty * 32 + tx;
        if (pvalid[col]) {
            float S1 = 0.f, S2 = 0.f, S3 = 0.f, Ss = 0.f;
#pragma unroll
            for (int u = 0; u < 8; u++) {
                S1 += r1[u][col]; S2 += r2s[u][col];
                S3 += r3[u][col]; Ss += rs[u][col];
            }
            int p = pid[col];
            g_part[slice][b][0][p] = S1;
            g_part[slice][b][1][p] = S2;
            g_part[slice][b][2][p] = S3;
            g_part[slice][b][3][p] = Ss;
        }
    }
}

__global__ void pi_final_kernel() {
    int b = blockIdx.y;
    int p = blockIdx.x * 256 + threadIdx.x;
    float v = 0.f;
    if (p < PIX65) {
        float S1 = 0.f, S2 = 0.f, S3 = 0.f, Ss = 0.f;
#pragma unroll
        for (int s = 0; s < NSLICE; s++) {
            S1 += g_part[s][b][0][p];
            S2 += g_part[s][b][1][p];
            S3 += g_part[s][b][2][p];
            Ss += g_part[s][b][3][p];
        }
        float inv = 1.f / S1;
        v = S2 * inv - logf(S1) - S3 * inv + logf(Ss);
    }
    __shared__ float red[256];
    int tid = threadIdx.x;
    red[tid] = v;
    __syncthreads();
    for (int o = 128; o; o >>= 1) {
        if (tid < o) red[tid] += red[tid + o];
        __syncthreads();
    }
    if (tid == 0) atomicAdd(&g_pi, (double)red[0]);
}

// ---------------------------------------------------------------------------
// prep: ONE block per (side,row); direct double stores (no atomics).
// ---------------------------------------------------------------------------
__global__ __launch_bounds__(256) void prep_kernel(const float* __restrict__ t_logit,
                                                   const float* __restrict__ s_logit) {
    int side = blockIdx.x;
    int row  = blockIdx.y;
    int tid  = threadIdx.x;

    float d = 0.f, wz = 0.f;
    float* dst = (side ? g_Ut : g_Us) + (size_t)row * PIX129;

    if (side == 0) {
        const float* src = s_logit + (size_t)row * PIX129;
        for (int k = tid; k < PIX129; k += 256) {
            float z = src[k];
            float u = __expf(z);
            dst[k] = u;
            d += u; wz += u * z;
        }
    } else {
        const float* src = t_logit + (size_t)row * PIX65;
        for (int k = tid; k < PIX129; k += 256) {
            int y = k / 129, x = k - y * 129;
            int y0 = y >> 1, x0 = x >> 1;
            int y1 = min(y0 + 1, 64), x1 = min(x0 + 1, 64);
            float wy = (y & 1) * 0.5f, wx = (x & 1) * 0.5f;
            float top = (1.f - wx) * src[y0 * 65 + x0] + wx * src[y0 * 65 + x1];
            float bot = (1.f - wx) * src[y1 * 65 + x0] + wx * src[y1 * 65 + x1];
            float z = (1.f - wy) * top + wy * bot;
            float u = __expf(z);
            dst[k] = u;
            d += u; wz += u * z;
        }
    }

    __shared__ float rd[256], rw[256];
    rd[tid] = d; rw[tid] = wz;
    __syncthreads();
    for (int o = 128; o; o >>= 1) {
        if (tid < o) { rd[tid] += rd[tid + o]; rw[tid] += rw[tid + o]; }
        __syncthreads();
    }
    if (tid == 0) {
        g_d[side][row]  = (double)rd[0];
        g_Wz[side][row] = (double)rw[0];
    }
}

// ---------------------------------------------------------------------------
__global__ void gram_kernel() {
    int side = blockIdx.z;
    int b    = blockIdx.y;
    int k0   = blockIdx.x * 512;
    const float* U = (side ? g_Ut : g_Us) + (size_t)b * NCH * PIX129;

    __shared__ __align__(8) float sm[NCH][514];
    int tid = threadIdx.x;
    for (int idx = tid; idx < NCH * 512; idx += 256) {
        int i = idx >> 9, kk = idx & 511;
        int k = k0 + kk;
        sm[i][kk] = (k < PIX129) ? U[(size_t)i * PIX129 + k] : 0.f;
    }
    __syncthreads();

    if (tid < 190) {
        int i = 0, t = tid;
        while (t >= NCH - i) { t -= NCH - i; i++; }
        int j = i + t;
        const u64* ri = (const u64*)&sm[i][0];
        const u64* rj = (const u64*)&sm[j][0];
        u64 acc2 = pack2(0.f, 0.f);
#pragma unroll 4
        for (int kk = 0; kk < 256; kk++) fma2(acc2, ri[kk], rj[kk]);
        float lo, hi;
        unpack2(lo, hi, acc2);
        atomicAdd(&g_R[side][b][tid], (double)(lo + hi));
    }
}

// ---------------------------------------------------------------------------
__global__ void finalize_kernel(float* __restrict__ out) {
    int tid = threadIdx.x;
    __shared__ double sE[2][NCH];
    __shared__ double sG[2][361];
    __shared__ double sS[2][361];
    __shared__ double sN[2][NCH];
    __shared__ double red[512];

    if (tid < 2 * NCH) {
        int side = tid / NCH, i = tid % NCH;
        double e = 0.0;
        for (int b = 0; b < NB; b++) {
            double d = g_d[side][b * NCH + i];
            e += g_Wz[side][b * NCH + i] / d - log(d);
        }
        sE[side][i] = e;
    }
    if (tid < 361) {
        int i = tid / NCH, j = tid % NCH;
        int mi = min(i, j), mj = max(i, j);
        int p = mi * NCH - mi * (mi - 1) / 2 + (mj - mi);
        for (int side = 0; side < 2; side++) {
            double g = 0.0;
            for (int b = 0; b < NB; b++)
                g += g_R[side][b][p] /
                     (g_d[side][b * NCH + i] * g_d[side][b * NCH + j]);
            sG[side][tid] = g;
        }
    }
    __syncthreads();
    if (tid < 361) {
        int i = tid / NCH, j = tid % NCH;
        int mx = max(i, j);
        sS[0][tid] = (sE[0][mx] - sG[0][tid]) / (double)NB;
        sS[1][tid] = (sE[1][mx] - sG[1][tid]) / (double)NB;
    }
    __syncthreads();
    if (tid < 2 * NCH) {
        int side = tid / NCH, i = tid % NCH;
        double s = 0.0;
        for (int j = 0; j < NCH; j++) {
            double v = sS[side][i * NCH + j];
            s += v * v;
        }
        double n = sqrt(s);
        sN[side][i] = (n > 1e-12) ? n : 1e-12;
    }
    __syncthreads();
    double v = 0.0;
    if (tid < 361) {
        int i = tid / NCH;
        double dd = sS[0][tid] / sN[0][i] - sS[1][tid] / sN[1][i];
        v = dd * dd;
    }
    red[tid] = v;
    __syncthreads();
    for (int o = 256; o; o >>= 1) {
        if (tid < o) red[tid] += red[tid + o];
        __syncthreads();
    }
    if (tid == 0) {
        out[0] = (float)(g_pi / 25958400.0);
        out[1] = (float)red[0];
    }
}

// ---------------------------------------------------------------------------
extern "C" void kernel_launch(void* const* d_in, const int* in_sizes, int n_in,
                              void* d_out, int out_size) {
    const float *ptr[6] = {nullptr, nullptr, nullptr, nullptr, nullptr, nullptr};
    const int want[6] = {1115136, 25958400, 642200, 2529912, 98304, 768};

    for (int i = 0; i < n_in; i++) {
        long long s = in_sizes[i];
        for (int k = 0; k < 6; k++) {
            if (s == (long long)want[k] || s == 4LL * want[k]) {
                if (!ptr[k]) ptr[k] = (const float*)d_in[i];
            }
        }
    }
    if (n_in >= 6) {
        for (int k = 0; k < 6; k++)
            if (!ptr[k]) ptr[k] = (const float*)d_in[k];
    }

    const float* s_out   = ptr[0];
    const float* t_out   = ptr[1];
    const float* t_logit = ptr[2];
    const float* s_logit = ptr[3];
    const float* conv_w  = ptr[4];
    const float* conv_b  = ptr[5];

    // Main stream: sbf (includes W convert + accumulator zeroing) -> fork.
    sbf_kernel<<<dim3(18, NB, 4), 256>>>(s_out, conv_w);
    cudaEventRecord(g_e1, 0);
    cudaStreamWaitEvent(g_s2, g_e1, 0);

    // Chain 1 (default stream): tensor GEMM + pi path.
    gemm_mma_kernel<<<dim3(18, 6, NB), 256>>>(conv_b);
    pi_partial_kernel<<<dim3(67, NB, NSLICE), dim3(32, 8)>>>(t_out);
    pi_final_kernel<<<dim3((PIX65 + 255) / 256, NB), 256>>>();

    // Chain 2 (side stream): lo path.
    prep_kernel<<<dim3(2, NB * NCH), 256, 0, g_s2>>>(t_logit, s_logit);
    gram_kernel<<<dim3((PIX129 + 511) / 512, NB, 2), 256, 0, g_s2>>>();

    cudaEventRecord(g_e2, g_s2);
    cudaStreamWaitEvent(0, g_e2, 0);
    finalize_kernel<<<1, 512>>>((float*)d_out);
}